// round 1
// baseline (speedup 1.0000x reference)
#include <cuda_runtime.h>
#include <math.h>

#define HF 100
#define WF 160
#define CIN 512
#define CC 512
#define NA 9
#define NPIX (HF*WF)
#define NANCH (NPIX*NA)      // 144000
#define PRE_NMS 6000
#define POST_NMS 300
#define NEGV -1e9f
#define IMG_H 1600.0f
#define IMG_W 2560.0f

// ---------------- device scratch (no allocations allowed) ----------------
__device__ float g_y[NPIX*CC];                 // conv output (relu'd), 32.8 MB
__device__ unsigned int g_hist1[65536];
__device__ unsigned int g_hist2[65536];
__device__ unsigned int g_binB, g_rank_before, g_T, g_G, g_need_eq;
__device__ unsigned int g_cnt_gt, g_eq_cnt;
__device__ unsigned long long g_pairs[8192];
__device__ unsigned int g_eq_idx[NANCH];
__device__ int   g_top_idx[PRE_NMS];
__device__ float g_top_score[PRE_NMS];
__device__ float g_by1[PRE_NMS], g_bx1[PRE_NMS], g_by2[PRE_NMS], g_bx2[PRE_NMS];
__device__ float g_nsc[PRE_NMS];

// ---------------- conv 3x3 512->512 + bias + relu ----------------
// tile: 8 rows x 32 cols pixels x 64 out channels. 256 threads, 8px x 8co per thread.
__global__ __launch_bounds__(256,2) void conv3_kernel(const float* __restrict__ fm,
                                                      const float* __restrict__ W1,
                                                      const float* __restrict__ b1) {
    __shared__ float  in_s[340*17];   // (10 x 34) pixels x 16 cin, padded to 17
    __shared__ float4 b_s[256];       // 16 cin x 64 co

    int t    = threadIdx.x;
    int co_g = t & 7;                 // 8 co-groups of 8 channels
    int px_g = t >> 3;                // 32 px-groups of 8 pixels
    int row0 = blockIdx.y * 8;
    int col0 = blockIdx.x * 32;
    int co0  = blockIdx.z * 64;

    float acc[8][8];
    #pragma unroll
    for (int i = 0; i < 8; i++)
        #pragma unroll
        for (int j = 0; j < 8; j++) acc[i][j] = 0.f;

    for (int cc0 = 0; cc0 < CIN; cc0 += 16) {
        __syncthreads();
        // load input halo tile [10][34][16]
        for (int idx = t; idx < 1360; idx += 256) {
            int pix = idx >> 2, v = idx & 3;
            int rr = pix / 34, ccol = pix - rr*34;
            int gr = row0 - 1 + rr, gc = col0 - 1 + ccol;
            float4 val = make_float4(0.f,0.f,0.f,0.f);
            if (gr >= 0 && gr < HF && gc >= 0 && gc < WF)
                val = *reinterpret_cast<const float4*>(fm + ((size_t)(gr*WF+gc)*CIN + cc0 + v*4));
            int sb = pix*17 + v*4;
            in_s[sb+0]=val.x; in_s[sb+1]=val.y; in_s[sb+2]=val.z; in_s[sb+3]=val.w;
        }
        __syncthreads();

        for (int tap = 0; tap < 9; tap++) {
            // weights for this tap: 16 cin x 64 co
            {
                int k = t >> 4, c4 = t & 15;
                b_s[t] = *reinterpret_cast<const float4*>(
                    W1 + ((size_t)(tap*CIN + cc0 + k)*CC + co0 + c4*4));
            }
            __syncthreads();

            int ky = tap/3, kx = tap - ky*3;
            int base[8];
            #pragma unroll
            for (int i = 0; i < 8; i++) {
                int p  = px_g*8 + i;
                int pr = p >> 5, pc = p & 31;
                base[i] = ((pr+ky)*34 + (pc+kx))*17;
            }
            #pragma unroll
            for (int kk = 0; kk < 16; kk++) {
                float4 w0 = b_s[kk*16 + co_g*2];
                float4 w1 = b_s[kk*16 + co_g*2 + 1];
                #pragma unroll
                for (int i = 0; i < 8; i++) {
                    float a = in_s[base[i]+kk];
                    acc[i][0] = fmaf(a, w0.x, acc[i][0]);
                    acc[i][1] = fmaf(a, w0.y, acc[i][1]);
                    acc[i][2] = fmaf(a, w0.z, acc[i][2]);
                    acc[i][3] = fmaf(a, w0.w, acc[i][3]);
                    acc[i][4] = fmaf(a, w1.x, acc[i][4]);
                    acc[i][5] = fmaf(a, w1.y, acc[i][5]);
                    acc[i][6] = fmaf(a, w1.z, acc[i][6]);
                    acc[i][7] = fmaf(a, w1.w, acc[i][7]);
                }
            }
            __syncthreads();
        }
    }

    float bias[8];
    #pragma unroll
    for (int j = 0; j < 8; j++) bias[j] = b1[co0 + co_g*8 + j];
    #pragma unroll
    for (int i = 0; i < 8; i++) {
        int p  = px_g*8 + i;
        int pr = p >> 5, pc = p & 31;
        int r = row0 + pr, c = col0 + pc;
        if (r < HF) {
            float4 o0, o1;
            o0.x = fmaxf(acc[i][0]+bias[0],0.f); o0.y = fmaxf(acc[i][1]+bias[1],0.f);
            o0.z = fmaxf(acc[i][2]+bias[2],0.f); o0.w = fmaxf(acc[i][3]+bias[3],0.f);
            o1.x = fmaxf(acc[i][4]+bias[4],0.f); o1.y = fmaxf(acc[i][5]+bias[5],0.f);
            o1.z = fmaxf(acc[i][6]+bias[6],0.f); o1.w = fmaxf(acc[i][7]+bias[7],0.f);
            float* dst = g_y + ((size_t)(r*WF+c)*CC + co0 + co_g*8);
            *reinterpret_cast<float4*>(dst)     = o0;
            *reinterpret_cast<float4*>(dst + 4) = o1;
        }
    }
}

// ---------------- 1x1 heads + softmax(9) + deltas ----------------
// 8 pixels per block, 45 outputs per pixel (9 cls + 36 reg)
__global__ __launch_bounds__(384) void heads_kernel(const float* __restrict__ Wc,
                                                    const float* __restrict__ bc,
                                                    const float* __restrict__ Wr,
                                                    const float* __restrict__ br,
                                                    float* __restrict__ out) {
    __shared__ float ys[8*128];
    __shared__ float ws[128*45];
    __shared__ float lg[8][9];

    int t  = threadIdx.x;
    int p0 = blockIdx.x * 8;
    int pp = t / 45, o = t - pp*45;

    float acc = 0.f;
    for (int c0 = 0; c0 < 512; c0 += 128) {
        __syncthreads();
        for (int idx = t; idx < 256; idx += 384) {
            int pix = idx >> 5, v = idx & 31;
            *reinterpret_cast<float4*>(ys + pix*128 + v*4) =
                *reinterpret_cast<const float4*>(g_y + (size_t)(p0+pix)*512 + c0 + v*4);
        }
        for (int idx = t; idx < 5760; idx += 384) {
            int k = idx / 45, oo = idx - k*45;
            ws[idx] = (oo < 9) ? Wc[(c0+k)*9 + oo] : Wr[(c0+k)*36 + (oo-9)];
        }
        __syncthreads();
        if (t < 360) {
            const float4* yv = reinterpret_cast<const float4*>(ys + pp*128);
            #pragma unroll 8
            for (int k4 = 0; k4 < 32; k4++) {
                float4 y4 = yv[k4];
                acc = fmaf(y4.x, ws[(k4*4+0)*45+o], acc);
                acc = fmaf(y4.y, ws[(k4*4+1)*45+o], acc);
                acc = fmaf(y4.z, ws[(k4*4+2)*45+o], acc);
                acc = fmaf(y4.w, ws[(k4*4+3)*45+o], acc);
            }
        }
    }

    if (t < 360) {
        int gp = p0 + pp;
        if (o < 9) lg[pp][o] = acc + bc[o];
        else       out[NANCH + (size_t)gp*36 + (o-9)] = acc + br[o-9];
    }
    __syncthreads();
    if (t < 360 && o < 9) {
        int gp = p0 + pp;
        float m = lg[pp][0];
        #pragma unroll
        for (int j = 1; j < 9; j++) m = fmaxf(m, lg[pp][j]);
        float sum = 0.f;
        #pragma unroll
        for (int j = 0; j < 9; j++) sum += expf(lg[pp][j]-m);
        out[(size_t)gp*9 + o] = expf(lg[pp][o]-m)/sum;
    }
}

// ---------------- exact top-k(6000) via 2-level radix ----------------
__global__ void zero_kernel() {
    int i = blockIdx.x*blockDim.x + threadIdx.x;
    if (i < 65536) g_hist1[i] = 0u;
    else if (i < 131072) g_hist2[i-65536] = 0u;
    else if (i == 131072) { g_cnt_gt = 0u; g_eq_cnt = 0u; }
}

__global__ void hist1_kernel(const float* __restrict__ out) {
    int i = blockIdx.x*blockDim.x + threadIdx.x;
    if (i < NANCH) {
        unsigned u = __float_as_uint(out[i]);   // scores are positive -> monotone bits
        atomicAdd(&g_hist1[u >> 16], 1u);
    }
}

__global__ void find_bin1_kernel() {
    __shared__ unsigned csum[1024];
    int t = threadIdx.x;
    unsigned s = 0;
    for (int b = 0; b < 64; b++) s += g_hist1[t*64+b];
    csum[t] = s;
    __syncthreads();
    if (t == 0) {
        unsigned cum = 0; int chunk = 0;
        for (int q = 1023; q >= 0; q--) {
            if (cum + csum[q] >= (unsigned)PRE_NMS) { chunk = q; break; }
            cum += csum[q];
        }
        unsigned B = 0;
        for (int b = chunk*64+63; b >= chunk*64; b--) {
            unsigned h = g_hist1[b];
            if (cum + h >= (unsigned)PRE_NMS) { B = (unsigned)b; break; }
            cum += h;
        }
        g_binB = B; g_rank_before = cum;
    }
}

__global__ void hist2_kernel(const float* __restrict__ out) {
    int i = blockIdx.x*blockDim.x + threadIdx.x;
    if (i < NANCH) {
        unsigned u = __float_as_uint(out[i]);
        if ((u >> 16) == g_binB) atomicAdd(&g_hist2[u & 0xFFFFu], 1u);
    }
}

__global__ void find_thresh_kernel() {
    __shared__ unsigned csum[1024];
    int t = threadIdx.x;
    unsigned s = 0;
    for (int b = 0; b < 64; b++) s += g_hist2[t*64+b];
    csum[t] = s;
    __syncthreads();
    if (t == 0) {
        unsigned cum = g_rank_before; int chunk = 0;
        for (int q = 1023; q >= 0; q--) {
            if (cum + csum[q] >= (unsigned)PRE_NMS) { chunk = q; break; }
            cum += csum[q];
        }
        unsigned L = 0;
        for (int b = chunk*64+63; b >= chunk*64; b--) {
            unsigned h = g_hist2[b];
            if (cum + h >= (unsigned)PRE_NMS) { L = (unsigned)b; break; }
            cum += h;
        }
        g_T = (g_binB << 16) | L;
        g_G = cum;
        g_need_eq = (unsigned)PRE_NMS - cum;
    }
}

__global__ void compact_kernel(const float* __restrict__ out) {
    int i = blockIdx.x*blockDim.x + threadIdx.x;
    if (i < NANCH) {
        unsigned u = __float_as_uint(out[i]);
        unsigned T = g_T;
        if (u > T) {
            unsigned pos = atomicAdd(&g_cnt_gt, 1u);
            g_pairs[pos] = (((unsigned long long)u) << 32) | (unsigned)(~(unsigned)i);
        } else if (u == T) {
            unsigned pos = atomicAdd(&g_eq_cnt, 1u);
            g_eq_idx[pos] = (unsigned)i;
        }
    }
}

// rank ties (== threshold) by ascending index; keep the first need_eq (jax tie rule)
__global__ void eq_rank_kernel() {
    unsigned E = g_eq_cnt, need = g_need_eq, G = g_G, T = g_T;
    for (unsigned e = blockIdx.x*blockDim.x + threadIdx.x; e < E; e += gridDim.x*blockDim.x) {
        unsigned idx = g_eq_idx[e];
        unsigned rank = 0;
        for (unsigned f = 0; f < E; f++) rank += (g_eq_idx[f] < idx) ? 1u : 0u;
        if (rank < need)
            g_pairs[G + rank] = (((unsigned long long)T) << 32) | (unsigned)(~idx);
    }
}

// bitonic sort 6000 (padded to 8192) descending by (score bits, ~idx) -> jax top_k order
__global__ void sort_kernel() {
    extern __shared__ unsigned long long sk[];
    int t = threadIdx.x;
    for (int j = t; j < 8192; j += 1024) sk[j] = (j < PRE_NMS) ? g_pairs[j] : 0ULL;
    __syncthreads();
    for (int k = 2; k <= 8192; k <<= 1) {
        for (int j = k >> 1; j > 0; j >>= 1) {
            for (int idx = t; idx < 8192; idx += 1024) {
                int ixj = idx ^ j;
                if (ixj > idx) {
                    unsigned long long a = sk[idx], b = sk[ixj];
                    bool desc = (idx & k) == 0;
                    if (desc ? (a < b) : (a > b)) { sk[idx] = b; sk[ixj] = a; }
                }
            }
            __syncthreads();
        }
    }
    for (int j = t; j < PRE_NMS; j += 1024) {
        unsigned long long p = sk[j];
        unsigned u = (unsigned)(p >> 32);
        unsigned idx = ~((unsigned)p);
        g_top_idx[j] = (int)idx;
        g_top_score[j] = __uint_as_float(u);
    }
}

// ---------------- decode + clip + validity ----------------
__global__ void decode_kernel(const float* __restrict__ amap, const float* __restrict__ out) {
    int j = blockIdx.x*blockDim.x + threadIdx.x;
    if (j < PRE_NMS) {
        int idx = g_top_idx[j];
        float4 a = *reinterpret_cast<const float4*>(amap + (size_t)idx*4);
        float4 d = *reinterpret_cast<const float4*>(out + NANCH + (size_t)idx*4);
        float cy = a.x + d.x * a.z;
        float cx = a.y + d.y * a.w;
        float hh = a.z * expf(d.z);
        float ww = a.w * expf(d.w);
        float y1 = cy - 0.5f*hh, x1 = cx - 0.5f*ww;
        float y2 = cy + 0.5f*hh, x2 = cx + 0.5f*ww;
        y1 = fmaxf(y1, 0.f); x1 = fmaxf(x1, 0.f);
        y2 = fminf(y2, IMG_H); x2 = fminf(x2, IMG_W);
        float bh = y2 - y1, bw = x2 - x1;
        bool valid = (bh >= 16.f) && (bw >= 16.f);
        g_by1[j] = y1; g_bx1[j] = x1; g_by2[j] = y2; g_bx2[j] = x2;
        g_nsc[j] = valid ? g_top_score[j] : NEGV;
    }
}

// ---------------- sequential NMS, 300 iterations, single block ----------------
__global__ void nms_kernel(float* __restrict__ out) {
    extern __shared__ float sm[];
    float *sy1 = sm, *sx1 = sm+6000, *sy2 = sm+12000, *sx2 = sm+18000;
    float *sar = sm+24000, *ssc = sm+30000;
    __shared__ float rs[32]; __shared__ int ri[32];
    __shared__ float c_bs;   __shared__ int c_bi;
    int t = threadIdx.x;

    for (int j = t; j < PRE_NMS; j += 1024) {
        float y1 = g_by1[j], x1 = g_bx1[j], y2 = g_by2[j], x2 = g_bx2[j];
        sy1[j] = y1; sx1[j] = x1; sy2[j] = y2; sx2[j] = x2;
        sar[j] = (y2 - y1) * (x2 - x1);
        ssc[j] = g_nsc[j];
    }
    __syncthreads();

    for (int r = 0; r < POST_NMS; r++) {
        float bs = -INFINITY; int bi = 0x7fffffff;
        for (int j = t; j < PRE_NMS; j += 1024) {
            float s = ssc[j];
            if (s > bs) { bs = s; bi = j; }
        }
        #pragma unroll
        for (int off = 16; off; off >>= 1) {
            float s2 = __shfl_down_sync(0xffffffffu, bs, off);
            int   i2 = __shfl_down_sync(0xffffffffu, bi, off);
            if (s2 > bs || (s2 == bs && i2 < bi)) { bs = s2; bi = i2; }
        }
        if ((t & 31) == 0) { rs[t >> 5] = bs; ri[t >> 5] = bi; }
        __syncthreads();
        if (t < 32) {
            bs = rs[t]; bi = ri[t];
            #pragma unroll
            for (int off = 16; off; off >>= 1) {
                float s2 = __shfl_down_sync(0xffffffffu, bs, off);
                int   i2 = __shfl_down_sync(0xffffffffu, bi, off);
                if (s2 > bs || (s2 == bs && i2 < bi)) { bs = s2; bi = i2; }
            }
            if (t == 0) { c_bs = bs; c_bi = bi; }
        }
        __syncthreads();
        int best = c_bi; float bscore = c_bs;
        bool ok = bscore > -5.0e8f;
        float by1 = sy1[best], bx1 = sx1[best], by2 = sy2[best], bx2 = sx2[best], ba = sar[best];
        if (ok) {
            for (int j = t; j < PRE_NMS; j += 1024) {
                float iy1 = fmaxf(sy1[j], by1), ix1 = fmaxf(sx1[j], bx1);
                float iy2 = fminf(sy2[j], by2), ix2 = fminf(sx2[j], bx2);
                float inter = fmaxf(iy2 - iy1, 0.f) * fmaxf(ix2 - ix1, 0.f);
                float iou = inter / (sar[j] + ba - inter + 1e-8f);
                if (iou > 0.7f) ssc[j] = NEGV;
            }
        }
        if (t == 0) {
            ssc[best] = NEGV;
            float4 row = ok ? make_float4(by1, bx1, by2, bx2) : make_float4(0.f,0.f,0.f,0.f);
            reinterpret_cast<float4*>(out + NANCH + NANCH*4)[r] = row;   // offset 720000
        }
        __syncthreads();
    }
}

// ---------------- launch ----------------
extern "C" void kernel_launch(void* const* d_in, const int* in_sizes, int n_in,
                              void* d_out, int out_size) {
    const float* fm   = (const float*)d_in[1];
    const float* amap = (const float*)d_in[2];
    const float* W1   = (const float*)d_in[3];
    const float* b1   = (const float*)d_in[4];
    const float* Wc   = (const float*)d_in[5];
    const float* bc   = (const float*)d_in[6];
    const float* Wr   = (const float*)d_in[7];
    const float* br   = (const float*)d_in[8];
    float* out = (float*)d_out;

    cudaFuncSetAttribute(sort_kernel, cudaFuncAttributeMaxDynamicSharedMemorySize, 8192*8);
    cudaFuncSetAttribute(nms_kernel,  cudaFuncAttributeMaxDynamicSharedMemorySize, 36000*4);

    zero_kernel<<<513, 256>>>();
    conv3_kernel<<<dim3(5, 13, 8), 256>>>(fm, W1, b1);
    heads_kernel<<<2000, 384>>>(Wc, bc, Wr, br, out);
    hist1_kernel<<<563, 256>>>(out);
    find_bin1_kernel<<<1, 1024>>>();
    hist2_kernel<<<563, 256>>>(out);
    find_thresh_kernel<<<1, 1024>>>();
    compact_kernel<<<563, 256>>>(out);
    eq_rank_kernel<<<32, 256>>>();
    sort_kernel<<<1, 1024, 8192*8>>>();
    decode_kernel<<<24, 256>>>(amap, out);
    nms_kernel<<<1, 1024, 36000*4>>>(out);
}

// round 3
// speedup vs baseline: 1.3065x; 1.3065x over previous
#include <cuda_runtime.h>
#include <math.h>
#include <stdint.h>

#define HF 100
#define WF 160
#define CIN 512
#define CC 512
#define NA 9
#define NPIX (HF*WF)
#define NANCH (NPIX*NA)      // 144000
#define PRE_NMS 6000
#define POST_NMS 300
#define NEGV -1e9f
#define IMG_H 1600.0f
#define IMG_W 2560.0f

// ---------------- device scratch (no allocations allowed) ----------------
__device__ float g_y[NPIX*CC];                 // conv output (relu'd), 32.8 MB
__device__ float g_fm_pack[NPIX*1024];         // [pix][hi(512) | lo(512)]
__device__ float g_w_pack[9*512*1024];         // [tap][co][hi(512)|lo(512)]
__device__ unsigned int g_hist1[65536];
__device__ unsigned int g_hist2[65536];
__device__ unsigned int g_binB, g_rank_before, g_T, g_G, g_need_eq;
__device__ unsigned int g_cnt_gt, g_eq_cnt;
__device__ unsigned long long g_pairs[8192];
__device__ unsigned int g_eq_idx[NANCH];
__device__ int   g_top_idx[PRE_NMS];
__device__ float g_top_score[PRE_NMS];
__device__ float g_by1[PRE_NMS], g_bx1[PRE_NMS], g_by2[PRE_NMS], g_bx2[PRE_NMS];
__device__ float g_nsc[PRE_NMS];

// ================= helpers =================
static __device__ __forceinline__ uint32_t smem_u32(const void* p) {
    uint32_t a;
    asm("{ .reg .u64 t; cvta.to.shared.u64 t, %1; cvt.u32.u64 %0, t; }" : "=r"(a) : "l"(p));
    return a;
}
static __device__ __forceinline__ float to_tf32(float x) {
    uint32_t u; asm("cvt.rna.tf32.f32 %0, %1;" : "=r"(u) : "f"(x));
    return __uint_as_float(u);
}
static __device__ __forceinline__ uint32_t lds32(uint32_t a) {
    uint32_t v; asm volatile("ld.shared.b32 %0, [%1];" : "=r"(v) : "r"(a));
    return v;
}
static __device__ __forceinline__ void cpa16(uint32_t dst, const void* src, uint32_t sz) {
    asm volatile("cp.async.cg.shared.global [%0], [%1], 16, %2;" :: "r"(dst), "l"(src), "r"(sz) : "memory");
}
static __device__ __forceinline__ void cpa16f(uint32_t dst, const void* src) {
    asm volatile("cp.async.cg.shared.global [%0], [%1], 16;" :: "r"(dst), "l"(src) : "memory");
}
#define CP_COMMIT() asm volatile("cp.async.commit_group;" ::: "memory")
#define CP_WAIT1()  asm volatile("cp.async.wait_group 1;" ::: "memory")

// mma.sync m16n8k8 tf32 (baseline PTX, sm_80+)
static __device__ __forceinline__ void mma8(float* d, const uint32_t* a, uint32_t b0, uint32_t b1) {
    asm volatile(
        "mma.sync.aligned.m16n8k8.row.col.f32.tf32.tf32.f32 "
        "{%0,%1,%2,%3}, {%4,%5,%6,%7}, {%8,%9}, {%0,%1,%2,%3};"
        : "+f"(d[0]), "+f"(d[1]), "+f"(d[2]), "+f"(d[3])
        : "r"(a[0]), "r"(a[1]), "r"(a[2]), "r"(a[3]), "r"(b0), "r"(b1));
}

// ================= packing (tf32 hi/lo split) =================
__global__ void pack_fm_kernel(const float* __restrict__ fm) {
    int i = blockIdx.x*blockDim.x + threadIdx.x;
    if (i < NPIX*512) {
        int p = i >> 9, cin = i & 511;
        float x = fm[i];
        float hi = to_tf32(x);
        float lo = to_tf32(x - hi);
        g_fm_pack[(size_t)p*1024 + cin]       = hi;
        g_fm_pack[(size_t)p*1024 + 512 + cin] = lo;
    }
}

__global__ void pack_w_kernel(const float* __restrict__ W1) {
    int i = blockIdx.x*blockDim.x + threadIdx.x;
    if (i < 9*512*512) {
        int tap = i >> 18, rem = i & 262143;
        int cin = rem >> 9, co = rem & 511;
        float x = W1[i];                       // [tap][cin][co]
        float hi = to_tf32(x);
        float lo = to_tf32(x - hi);
        size_t base = ((size_t)tap*512 + co)*1024;
        g_w_pack[base + cin]       = hi;
        g_w_pack[base + 512 + cin] = lo;
    }
}

// ================= conv 3x3 512->512 via mma.sync tf32 (3x split) =================
// CTA tile: 8x16 pixel block (halo 10x18) x 128 co. 256 threads, 8 warps (4 M x 2 N).
// K loop: 32 cin-chunks of 16 x 9 taps = 288 iterations; A halo chunk reused over 9 taps.
#define SEG_A 14400            // 180 px * 80B
#define ABUF  28800            // hi+lo
#define SEG_B 10240            // 128 co * 80B
#define BBUF  20480
#define BOFF  57600            // B buffers start after 2 A buffers
#define CONV_SMEM (BOFF + 2*BBUF)   // 98560 B

__global__ __launch_bounds__(256, 2) void conv_mma_kernel(const float* __restrict__ b1) {
    extern __shared__ char smraw[];
    uint32_t sb = smem_u32(smraw);
    int t = threadIdx.x;
    int row0 = blockIdx.y * 8;
    int col0 = blockIdx.x * 16;
    int n0   = blockIdx.z * 128;
    int wid = t >> 5, lane = t & 31;
    int g = lane >> 2, tg = lane & 3;
    int wm = wid >> 1, wn = wid & 1;

    // A fragment row bases (within halo, before tap shift): pixel (pr, pc) = (2wm+mt, g or g+8)
    uint32_t hA[2][2];
    #pragma unroll
    for (int mt = 0; mt < 2; mt++) {
        int pr = 2*wm + mt;
        hA[mt][0] = (uint32_t)((pr*18 + g    )*80 + tg*4);
        hA[mt][1] = (uint32_t)((pr*18 + g + 8)*80 + tg*4);
    }
    uint32_t nbase = (uint32_t)((wn*64 + g)*80 + tg*4);

    float acc[2][8][4];
    #pragma unroll
    for (int mt = 0; mt < 2; mt++)
        #pragma unroll
        for (int nt = 0; nt < 8; nt++)
            #pragma unroll
            for (int v = 0; v < 4; v++) acc[mt][nt][v] = 0.f;

    auto loadA = [&](int buf, int cc) {
        uint32_t Ab = sb + buf*ABUF;
        #pragma unroll 1
        for (int o = t; o < 1440; o += 256) {
            int pix = o >> 3, part = o & 7;
            int seg = part >> 2, k4 = part & 3;
            int hr = pix / 18, hc = pix - hr*18;
            int gr = row0 - 1 + hr, gc = col0 - 1 + hc;
            bool v = ((unsigned)gr < (unsigned)HF) && ((unsigned)gc < (unsigned)WF);
            const float* src = v ? (g_fm_pack + (size_t)(gr*WF + gc)*1024 + seg*512 + cc*16 + k4*4)
                                 : g_fm_pack;
            cpa16(Ab + (uint32_t)(seg*SEG_A + pix*80 + k4*16), src, v ? 16u : 0u);
        }
    };
    auto loadB = [&](int buf, int tap, int cc) {
        uint32_t Bb = sb + BOFF + buf*BBUF;
        #pragma unroll 1
        for (int o = t; o < 1024; o += 256) {
            int co = o >> 3, part = o & 7;
            int seg = part >> 2, k4 = part & 3;
            const float* src = g_w_pack + ((size_t)tap*512 + n0 + co)*1024 + seg*512 + cc*16 + k4*4;
            cpa16f(Bb + (uint32_t)(seg*SEG_B + co*80 + k4*16), src);
        }
    };

    // prologue: chunk 0 A + iteration 0 B
    loadA(0, 0);
    loadB(0, 0, 0);
    CP_COMMIT();

    for (int it = 0; it < 288; it++) {
        int nxt = it + 1;
        if (nxt < 288) {
            int ncc = nxt / 9, ntap = nxt - ncc*9;
            if (ntap == 0) loadA(ncc & 1, ncc);
            loadB(nxt & 1, ntap, ncc);
        }
        CP_COMMIT();
        CP_WAIT1();
        __syncthreads();

        int cc = it / 9, tap = it - cc*9;
        uint32_t tapoff = (uint32_t)((tap/3)*18*80 + (tap%3)*80);   // (1+dy)*18+(1+dx) rows of 80B
        uint32_t Ab = sb + (cc & 1)*ABUF + tapoff;
        uint32_t Bb = sb + BOFF + (it & 1)*BBUF + nbase;

        #pragma unroll
        for (int ks = 0; ks < 2; ks++) {
            uint32_t ko = ks * 32;
            uint32_t ah[2][4], al[2][4];
            #pragma unroll
            for (int mt = 0; mt < 2; mt++) {
                uint32_t r0 = Ab + hA[mt][0] + ko;
                uint32_t r1 = Ab + hA[mt][1] + ko;
                ah[mt][0] = lds32(r0);          ah[mt][1] = lds32(r1);
                ah[mt][2] = lds32(r0 + 16);     ah[mt][3] = lds32(r1 + 16);
                al[mt][0] = lds32(r0 + SEG_A);      al[mt][1] = lds32(r1 + SEG_A);
                al[mt][2] = lds32(r0 + SEG_A + 16); al[mt][3] = lds32(r1 + SEG_A + 16);
            }
            #pragma unroll
            for (int nt = 0; nt < 8; nt++) {
                uint32_t bo = Bb + nt*640 + ko;
                uint32_t bh0 = lds32(bo), bh1 = lds32(bo + 16);
                uint32_t bl0 = lds32(bo + SEG_B), bl1 = lds32(bo + SEG_B + 16);
                mma8(acc[0][nt], ah[0], bh0, bh1);
                mma8(acc[1][nt], ah[1], bh0, bh1);
                mma8(acc[0][nt], al[0], bh0, bh1);
                mma8(acc[1][nt], al[1], bh0, bh1);
                mma8(acc[0][nt], ah[0], bl0, bl1);
                mma8(acc[1][nt], ah[1], bl0, bl1);
            }
        }
        __syncthreads();
    }

    // epilogue: bias + relu + store
    #pragma unroll
    for (int mt = 0; mt < 2; mt++) {
        int gr = row0 + 2*wm + mt;
        if (gr < HF) {
            int pixA = gr*WF + col0 + g;
            int pixB = pixA + 8;
            #pragma unroll
            for (int nt = 0; nt < 8; nt++) {
                int col = n0 + wn*64 + nt*8 + 2*tg;
                float bb0 = b1[col], bb1 = b1[col + 1];
                float2 oA, oB;
                oA.x = fmaxf(acc[mt][nt][0] + bb0, 0.f);
                oA.y = fmaxf(acc[mt][nt][1] + bb1, 0.f);
                oB.x = fmaxf(acc[mt][nt][2] + bb0, 0.f);
                oB.y = fmaxf(acc[mt][nt][3] + bb1, 0.f);
                *reinterpret_cast<float2*>(g_y + (size_t)pixA*512 + col) = oA;
                *reinterpret_cast<float2*>(g_y + (size_t)pixB*512 + col) = oB;
            }
        }
    }
}

// ---------------- 1x1 heads + softmax(9) + deltas ----------------
__global__ __launch_bounds__(384) void heads_kernel(const float* __restrict__ Wc,
                                                    const float* __restrict__ bc,
                                                    const float* __restrict__ Wr,
                                                    const float* __restrict__ br,
                                                    float* __restrict__ out) {
    __shared__ float ys[8*128];
    __shared__ float ws[128*45];
    __shared__ float lg[8][9];

    int t  = threadIdx.x;
    int p0 = blockIdx.x * 8;
    int pp = t / 45, o = t - pp*45;

    float acc = 0.f;
    for (int c0 = 0; c0 < 512; c0 += 128) {
        __syncthreads();
        for (int idx = t; idx < 256; idx += 384) {
            int pix = idx >> 5, v = idx & 31;
            *reinterpret_cast<float4*>(ys + pix*128 + v*4) =
                *reinterpret_cast<const float4*>(g_y + (size_t)(p0+pix)*512 + c0 + v*4);
        }
        for (int idx = t; idx < 5760; idx += 384) {
            int k = idx / 45, oo = idx - k*45;
            ws[idx] = (oo < 9) ? Wc[(c0+k)*9 + oo] : Wr[(c0+k)*36 + (oo-9)];
        }
        __syncthreads();
        if (t < 360) {
            const float4* yv = reinterpret_cast<const float4*>(ys + pp*128);
            #pragma unroll 8
            for (int k4 = 0; k4 < 32; k4++) {
                float4 y4 = yv[k4];
                acc = fmaf(y4.x, ws[(k4*4+0)*45+o], acc);
                acc = fmaf(y4.y, ws[(k4*4+1)*45+o], acc);
                acc = fmaf(y4.z, ws[(k4*4+2)*45+o], acc);
                acc = fmaf(y4.w, ws[(k4*4+3)*45+o], acc);
            }
        }
    }

    if (t < 360) {
        int gp = p0 + pp;
        if (o < 9) lg[pp][o] = acc + bc[o];
        else       out[NANCH + (size_t)gp*36 + (o-9)] = acc + br[o-9];
    }
    __syncthreads();
    if (t < 360 && o < 9) {
        int gp = p0 + pp;
        float m = lg[pp][0];
        #pragma unroll
        for (int j = 1; j < 9; j++) m = fmaxf(m, lg[pp][j]);
        float sum = 0.f;
        #pragma unroll
        for (int j = 0; j < 9; j++) sum += expf(lg[pp][j]-m);
        out[(size_t)gp*9 + o] = expf(lg[pp][o]-m)/sum;
    }
}

// ---------------- exact top-k(6000) via 2-level radix ----------------
__global__ void zero_kernel() {
    int i = blockIdx.x*blockDim.x + threadIdx.x;
    if (i < 65536) g_hist1[i] = 0u;
    else if (i < 131072) g_hist2[i-65536] = 0u;
    else if (i == 131072) { g_cnt_gt = 0u; g_eq_cnt = 0u; }
}

__global__ void hist1_kernel(const float* __restrict__ out) {
    int i = blockIdx.x*blockDim.x + threadIdx.x;
    if (i < NANCH) {
        unsigned u = __float_as_uint(out[i]);
        atomicAdd(&g_hist1[u >> 16], 1u);
    }
}

__global__ void find_bin1_kernel() {
    __shared__ unsigned csum[1024];
    int t = threadIdx.x;
    unsigned s = 0;
    for (int b = 0; b < 64; b++) s += g_hist1[t*64+b];
    csum[t] = s;
    __syncthreads();
    if (t == 0) {
        unsigned cum = 0; int chunk = 0;
        for (int q = 1023; q >= 0; q--) {
            if (cum + csum[q] >= (unsigned)PRE_NMS) { chunk = q; break; }
            cum += csum[q];
        }
        unsigned B = 0;
        for (int b = chunk*64+63; b >= chunk*64; b--) {
            unsigned h = g_hist1[b];
            if (cum + h >= (unsigned)PRE_NMS) { B = (unsigned)b; break; }
            cum += h;
        }
        g_binB = B; g_rank_before = cum;
    }
}

__global__ void hist2_kernel(const float* __restrict__ out) {
    int i = blockIdx.x*blockDim.x + threadIdx.x;
    if (i < NANCH) {
        unsigned u = __float_as_uint(out[i]);
        if ((u >> 16) == g_binB) atomicAdd(&g_hist2[u & 0xFFFFu], 1u);
    }
}

__global__ void find_thresh_kernel() {
    __shared__ unsigned csum[1024];
    int t = threadIdx.x;
    unsigned s = 0;
    for (int b = 0; b < 64; b++) s += g_hist2[t*64+b];
    csum[t] = s;
    __syncthreads();
    if (t == 0) {
        unsigned cum = g_rank_before; int chunk = 0;
        for (int q = 1023; q >= 0; q--) {
            if (cum + csum[q] >= (unsigned)PRE_NMS) { chunk = q; break; }
            cum += csum[q];
        }
        unsigned L = 0;
        for (int b = chunk*64+63; b >= chunk*64; b--) {
            unsigned h = g_hist2[b];
            if (cum + h >= (unsigned)PRE_NMS) { L = (unsigned)b; break; }
            cum += h;
        }
        g_T = (g_binB << 16) | L;
        g_G = cum;
        g_need_eq = (unsigned)PRE_NMS - cum;
    }
}

__global__ void compact_kernel(const float* __restrict__ out) {
    int i = blockIdx.x*blockDim.x + threadIdx.x;
    if (i < NANCH) {
        unsigned u = __float_as_uint(out[i]);
        unsigned T = g_T;
        if (u > T) {
            unsigned pos = atomicAdd(&g_cnt_gt, 1u);
            g_pairs[pos] = (((unsigned long long)u) << 32) | (unsigned)(~(unsigned)i);
        } else if (u == T) {
            unsigned pos = atomicAdd(&g_eq_cnt, 1u);
            g_eq_idx[pos] = (unsigned)i;
        }
    }
}

__global__ void eq_rank_kernel() {
    unsigned E = g_eq_cnt, need = g_need_eq, G = g_G, T = g_T;
    for (unsigned e = blockIdx.x*blockDim.x + threadIdx.x; e < E; e += gridDim.x*blockDim.x) {
        unsigned idx = g_eq_idx[e];
        unsigned rank = 0;
        for (unsigned f = 0; f < E; f++) rank += (g_eq_idx[f] < idx) ? 1u : 0u;
        if (rank < need)
            g_pairs[G + rank] = (((unsigned long long)T) << 32) | (unsigned)(~idx);
    }
}

__global__ void sort_kernel() {
    extern __shared__ unsigned long long sk[];
    int t = threadIdx.x;
    for (int j = t; j < 8192; j += 1024) sk[j] = (j < PRE_NMS) ? g_pairs[j] : 0ULL;
    __syncthreads();
    for (int k = 2; k <= 8192; k <<= 1) {
        for (int j = k >> 1; j > 0; j >>= 1) {
            for (int idx = t; idx < 8192; idx += 1024) {
                int ixj = idx ^ j;
                if (ixj > idx) {
                    unsigned long long a = sk[idx], b = sk[ixj];
                    bool desc = (idx & k) == 0;
                    if (desc ? (a < b) : (a > b)) { sk[idx] = b; sk[ixj] = a; }
                }
            }
            __syncthreads();
        }
    }
    for (int j = t; j < PRE_NMS; j += 1024) {
        unsigned long long p = sk[j];
        unsigned u = (unsigned)(p >> 32);
        unsigned idx = ~((unsigned)p);
        g_top_idx[j] = (int)idx;
        g_top_score[j] = __uint_as_float(u);
    }
}

__global__ void decode_kernel(const float* __restrict__ amap, const float* __restrict__ out) {
    int j = blockIdx.x*blockDim.x + threadIdx.x;
    if (j < PRE_NMS) {
        int idx = g_top_idx[j];
        float4 a = *reinterpret_cast<const float4*>(amap + (size_t)idx*4);
        float4 d = *reinterpret_cast<const float4*>(out + NANCH + (size_t)idx*4);
        float cy = a.x + d.x * a.z;
        float cx = a.y + d.y * a.w;
        float hh = a.z * expf(d.z);
        float ww = a.w * expf(d.w);
        float y1 = cy - 0.5f*hh, x1 = cx - 0.5f*ww;
        float y2 = cy + 0.5f*hh, x2 = cx + 0.5f*ww;
        y1 = fmaxf(y1, 0.f); x1 = fmaxf(x1, 0.f);
        y2 = fminf(y2, IMG_H); x2 = fminf(x2, IMG_W);
        float bh = y2 - y1, bw = x2 - x1;
        bool valid = (bh >= 16.f) && (bw >= 16.f);
        g_by1[j] = y1; g_bx1[j] = x1; g_by2[j] = y2; g_bx2[j] = x2;
        g_nsc[j] = valid ? g_top_score[j] : NEGV;
    }
}

__global__ void nms_kernel(float* __restrict__ out) {
    extern __shared__ float sm[];
    float *sy1 = sm, *sx1 = sm+6000, *sy2 = sm+12000, *sx2 = sm+18000;
    float *sar = sm+24000, *ssc = sm+30000;
    __shared__ float rs[32]; __shared__ int ri[32];
    __shared__ float c_bs;   __shared__ int c_bi;
    int t = threadIdx.x;

    for (int j = t; j < PRE_NMS; j += 1024) {
        float y1 = g_by1[j], x1 = g_bx1[j], y2 = g_by2[j], x2 = g_bx2[j];
        sy1[j] = y1; sx1[j] = x1; sy2[j] = y2; sx2[j] = x2;
        sar[j] = (y2 - y1) * (x2 - x1);
        ssc[j] = g_nsc[j];
    }
    __syncthreads();

    for (int r = 0; r < POST_NMS; r++) {
        float bs = -INFINITY; int bi = 0x7fffffff;
        for (int j = t; j < PRE_NMS; j += 1024) {
            float s = ssc[j];
            if (s > bs) { bs = s; bi = j; }
        }
        #pragma unroll
        for (int off = 16; off; off >>= 1) {
            float s2 = __shfl_down_sync(0xffffffffu, bs, off);
            int   i2 = __shfl_down_sync(0xffffffffu, bi, off);
            if (s2 > bs || (s2 == bs && i2 < bi)) { bs = s2; bi = i2; }
        }
        if ((t & 31) == 0) { rs[t >> 5] = bs; ri[t >> 5] = bi; }
        __syncthreads();
        if (t < 32) {
            bs = rs[t]; bi = ri[t];
            #pragma unroll
            for (int off = 16; off; off >>= 1) {
                float s2 = __shfl_down_sync(0xffffffffu, bs, off);
                int   i2 = __shfl_down_sync(0xffffffffu, bi, off);
                if (s2 > bs || (s2 == bs && i2 < bi)) { bs = s2; bi = i2; }
            }
            if (t == 0) { c_bs = bs; c_bi = bi; }
        }
        __syncthreads();
        int best = c_bi; float bscore = c_bs;
        bool ok = bscore > -5.0e8f;
        float by1 = sy1[best], bx1 = sx1[best], by2 = sy2[best], bx2 = sx2[best], ba = sar[best];
        if (ok) {
            for (int j = t; j < PRE_NMS; j += 1024) {
                float iy1 = fmaxf(sy1[j], by1), ix1 = fmaxf(sx1[j], bx1);
                float iy2 = fminf(sy2[j], by2), ix2 = fminf(sx2[j], bx2);
                float inter = fmaxf(iy2 - iy1, 0.f) * fmaxf(ix2 - ix1, 0.f);
                float iou = inter / (sar[j] + ba - inter + 1e-8f);
                if (iou > 0.7f) ssc[j] = NEGV;
            }
        }
        if (t == 0) {
            ssc[best] = NEGV;
            float4 row = ok ? make_float4(by1, bx1, by2, bx2) : make_float4(0.f,0.f,0.f,0.f);
            reinterpret_cast<float4*>(out + NANCH + NANCH*4)[r] = row;
        }
        __syncthreads();
    }
}

// ---------------- launch ----------------
extern "C" void kernel_launch(void* const* d_in, const int* in_sizes, int n_in,
                              void* d_out, int out_size) {
    const float* fm   = (const float*)d_in[1];
    const float* amap = (const float*)d_in[2];
    const float* W1   = (const float*)d_in[3];
    const float* b1   = (const float*)d_in[4];
    const float* Wc   = (const float*)d_in[5];
    const float* bc   = (const float*)d_in[6];
    const float* Wr   = (const float*)d_in[7];
    const float* br   = (const float*)d_in[8];
    float* out = (float*)d_out;

    cudaFuncSetAttribute(sort_kernel, cudaFuncAttributeMaxDynamicSharedMemorySize, 8192*8);
    cudaFuncSetAttribute(nms_kernel,  cudaFuncAttributeMaxDynamicSharedMemorySize, 36000*4);
    cudaFuncSetAttribute(conv_mma_kernel, cudaFuncAttributeMaxDynamicSharedMemorySize, CONV_SMEM);

    pack_fm_kernel<<<32000, 256>>>(fm);
    pack_w_kernel<<<9216, 256>>>(W1);
    zero_kernel<<<513, 256>>>();

    conv_mma_kernel<<<dim3(10, 13, 4), 256, CONV_SMEM>>>(b1);

    heads_kernel<<<2000, 384>>>(Wc, bc, Wr, br, out);
    hist1_kernel<<<563, 256>>>(out);
    find_bin1_kernel<<<1, 1024>>>();
    hist2_kernel<<<563, 256>>>(out);
    find_thresh_kernel<<<1, 1024>>>();
    compact_kernel<<<563, 256>>>(out);
    eq_rank_kernel<<<32, 256>>>();
    sort_kernel<<<1, 1024, 8192*8>>>();
    decode_kernel<<<24, 256>>>(amap, out);
    nms_kernel<<<1, 1024, 36000*4>>>(out);
}

// round 4
// speedup vs baseline: 1.3662x; 1.0457x over previous
#include <cuda_runtime.h>
#include <math.h>
#include <stdint.h>

#define HF 100
#define WF 160
#define CIN 512
#define CC 512
#define NA 9
#define NPIX (HF*WF)
#define NANCH (NPIX*NA)      // 144000
#define PRE_NMS 6000
#define POST_NMS 300
#define NEGV -1e9f
#define IMG_H 1600.0f
#define IMG_W 2560.0f

// ---------------- device scratch (no allocations allowed) ----------------
__device__ float g_y[NPIX*CC];                 // conv output (relu'd), 32.8 MB
__device__ float g_fm_pack[NPIX*1024];         // [pix][hi(512) | lo(512)]
__device__ float g_w_pack[9*512*1024];         // [tap][co][hi(512)|lo(512)]
__device__ unsigned int g_hist1[65536];
__device__ unsigned int g_hist2[65536];
__device__ unsigned int g_binB, g_rank_before, g_T, g_G, g_need_eq;
__device__ unsigned int g_cnt_gt, g_eq_cnt;
__device__ unsigned long long g_pairs[8192];
__device__ unsigned int g_eq_idx[NANCH];
__device__ int   g_top_idx[PRE_NMS];
__device__ float g_top_score[PRE_NMS];
__device__ float g_by1[PRE_NMS], g_bx1[PRE_NMS], g_by2[PRE_NMS], g_bx2[PRE_NMS];
__device__ float g_nsc[PRE_NMS];

// ================= helpers =================
static __device__ __forceinline__ uint32_t smem_u32(const void* p) {
    uint32_t a;
    asm("{ .reg .u64 t; cvta.to.shared.u64 t, %1; cvt.u32.u64 %0, t; }" : "=r"(a) : "l"(p));
    return a;
}
static __device__ __forceinline__ float to_tf32(float x) {
    uint32_t u; asm("cvt.rna.tf32.f32 %0, %1;" : "=r"(u) : "f"(x));
    return __uint_as_float(u);
}
static __device__ __forceinline__ uint32_t lds32(uint32_t a) {
    uint32_t v; asm volatile("ld.shared.b32 %0, [%1];" : "=r"(v) : "r"(a));
    return v;
}
static __device__ __forceinline__ void cpa16(uint32_t dst, const void* src, uint32_t sz) {
    asm volatile("cp.async.cg.shared.global [%0], [%1], 16, %2;" :: "r"(dst), "l"(src), "r"(sz) : "memory");
}
static __device__ __forceinline__ void cpa16f(uint32_t dst, const void* src) {
    asm volatile("cp.async.cg.shared.global [%0], [%1], 16;" :: "r"(dst), "l"(src) : "memory");
}
#define CP_COMMIT() asm volatile("cp.async.commit_group;" ::: "memory")
#define CP_WAIT1()  asm volatile("cp.async.wait_group 1;" ::: "memory")

// mma.sync m16n8k8 tf32 (baseline PTX, sm_80+)
static __device__ __forceinline__ void mma8(float* d, const uint32_t* a, uint32_t b0, uint32_t b1) {
    asm volatile(
        "mma.sync.aligned.m16n8k8.row.col.f32.tf32.tf32.f32 "
        "{%0,%1,%2,%3}, {%4,%5,%6,%7}, {%8,%9}, {%0,%1,%2,%3};"
        : "+f"(d[0]), "+f"(d[1]), "+f"(d[2]), "+f"(d[3])
        : "r"(a[0]), "r"(a[1]), "r"(a[2]), "r"(a[3]), "r"(b0), "r"(b1));
}

// ================= packing (tf32 hi/lo split) =================
__global__ void pack_fm_kernel(const float* __restrict__ fm) {
    int i = blockIdx.x*blockDim.x + threadIdx.x;
    if (i < NPIX*512) {
        int p = i >> 9, cin = i & 511;
        float x = fm[i];
        float hi = to_tf32(x);
        float lo = to_tf32(x - hi);
        g_fm_pack[(size_t)p*1024 + cin]       = hi;
        g_fm_pack[(size_t)p*1024 + 512 + cin] = lo;
    }
}

__global__ void pack_w_kernel(const float* __restrict__ W1) {
    int i = blockIdx.x*blockDim.x + threadIdx.x;
    if (i < 9*512*512) {
        int tap = i >> 18, rem = i & 262143;
        int cin = rem >> 9, co = rem & 511;
        float x = W1[i];                       // [tap][cin][co]
        float hi = to_tf32(x);
        float lo = to_tf32(x - hi);
        size_t base = ((size_t)tap*512 + co)*1024;
        g_w_pack[base + cin]       = hi;
        g_w_pack[base + 512 + cin] = lo;
    }
}

// ================= conv 3x3 512->512 via mma.sync tf32 (3x split) =================
// CTA tile: 8x16 pixel block (halo 10x18) x 64 co. 256 threads, 8 warps (4 M x 2 N).
// K loop: 32 cin-chunks of 16 x 9 taps = 288 iterations; A reused across 9 taps.
// Pipeline: A double-buffer (per cin-chunk), B triple-buffer (per iteration), 1 barrier/iter.
#define SEG_A 14400            // 180 px * 80B
#define ABUF  28800            // hi+lo
#define SEG_B 5120             // 64 co * 80B
#define BSTG  10240            // hi+lo per stage
#define BOFF  57600            // B buffers after 2 A buffers
#define CONV_SMEM (BOFF + 3*BSTG)   // 88320 B

__global__ __launch_bounds__(256, 2) void conv_mma_kernel(const float* __restrict__ b1) {
    extern __shared__ char smraw[];
    uint32_t sb = smem_u32(smraw);
    int t = threadIdx.x;
    int row0 = blockIdx.y * 8;
    int col0 = blockIdx.x * 16;
    int n0   = blockIdx.z * 64;
    int wid = t >> 5, lane = t & 31;
    int g = lane >> 2, tg = lane & 3;
    int wm = wid >> 1, wn = wid & 1;

    uint32_t hA[2][2];
    #pragma unroll
    for (int mt = 0; mt < 2; mt++) {
        int pr = 2*wm + mt;
        hA[mt][0] = (uint32_t)((pr*18 + g    )*80 + tg*4);
        hA[mt][1] = (uint32_t)((pr*18 + g + 8)*80 + tg*4);
    }
    uint32_t nbase = (uint32_t)((wn*32 + g)*80 + tg*4);

    float acc[2][4][4];
    #pragma unroll
    for (int mt = 0; mt < 2; mt++)
        #pragma unroll
        for (int nt = 0; nt < 4; nt++)
            #pragma unroll
            for (int v = 0; v < 4; v++) acc[mt][nt][v] = 0.f;

    auto loadA = [&](int buf, int cc) {
        uint32_t Ab = sb + buf*ABUF;
        #pragma unroll 1
        for (int o = t; o < 1440; o += 256) {
            int pix = o >> 3, part = o & 7;
            int seg = part >> 2, k4 = part & 3;
            int hr = pix / 18, hc = pix - hr*18;
            int gr = row0 - 1 + hr, gc = col0 - 1 + hc;
            bool v = ((unsigned)gr < (unsigned)HF) && ((unsigned)gc < (unsigned)WF);
            const float* src = v ? (g_fm_pack + (size_t)(gr*WF + gc)*1024 + seg*512 + cc*16 + k4*4)
                                 : g_fm_pack;
            cpa16(Ab + (uint32_t)(seg*SEG_A + pix*80 + k4*16), src, v ? 16u : 0u);
        }
    };
    auto loadB = [&](int buf, int tap, int cc) {
        uint32_t Bb = sb + BOFF + buf*BSTG;
        {
            int o = t, o2 = t + 256;
            int co = o >> 3, part = o & 7;
            int seg = part >> 2, k4 = part & 3;
            cpa16f(Bb + (uint32_t)(seg*SEG_B + co*80 + k4*16),
                   g_w_pack + ((size_t)tap*512 + n0 + co)*1024 + seg*512 + cc*16 + k4*4);
            int co2 = o2 >> 3, part2 = o2 & 7;
            int seg2 = part2 >> 2, k42 = part2 & 3;
            cpa16f(Bb + (uint32_t)(seg2*SEG_B + co2*80 + k42*16),
                   g_w_pack + ((size_t)tap*512 + n0 + co2)*1024 + seg2*512 + cc*16 + k42*4);
        }
    };

    // prologue: groups for it=0 and it=1
    loadA(0, 0);
    loadB(0, 0, 0);
    CP_COMMIT();
    loadB(1, 1, 0);
    CP_COMMIT();

    for (int it = 0; it < 288; it++) {
        CP_WAIT1();                 // group(it) complete (group(it+1) may be pending)
        __syncthreads();            // + all warps done reading stage (it-1)
        if (it < 286) {
            int nx = it + 2;
            int ncc = nx / 9, ntap = nx - ncc*9;
            if (ntap == 0) loadA(ncc & 1, ncc);
            loadB(nx % 3, ntap, ncc);
        }
        CP_COMMIT();

        int cc = it / 9, tap = it - cc*9;
        uint32_t tapoff = (uint32_t)((tap/3)*18*80 + (tap%3)*80);
        uint32_t Ab = sb + (cc & 1)*ABUF + tapoff;
        uint32_t Bb = sb + BOFF + (it % 3)*BSTG + nbase;

        #pragma unroll
        for (int ks = 0; ks < 2; ks++) {
            uint32_t ko = ks * 32;
            uint32_t ah[2][4], al[2][4];
            #pragma unroll
            for (int mt = 0; mt < 2; mt++) {
                uint32_t r0 = Ab + hA[mt][0] + ko;
                uint32_t r1 = Ab + hA[mt][1] + ko;
                ah[mt][0] = lds32(r0);          ah[mt][1] = lds32(r1);
                ah[mt][2] = lds32(r0 + 16);     ah[mt][3] = lds32(r1 + 16);
                al[mt][0] = lds32(r0 + SEG_A);      al[mt][1] = lds32(r1 + SEG_A);
                al[mt][2] = lds32(r0 + SEG_A + 16); al[mt][3] = lds32(r1 + SEG_A + 16);
            }
            #pragma unroll
            for (int nt = 0; nt < 4; nt++) {
                uint32_t bo = Bb + nt*640 + ko;
                uint32_t bh0 = lds32(bo), bh1 = lds32(bo + 16);
                uint32_t bl0 = lds32(bo + SEG_B), bl1 = lds32(bo + SEG_B + 16);
                mma8(acc[0][nt], ah[0], bh0, bh1);
                mma8(acc[1][nt], ah[1], bh0, bh1);
                mma8(acc[0][nt], al[0], bh0, bh1);
                mma8(acc[1][nt], al[1], bh0, bh1);
                mma8(acc[0][nt], ah[0], bl0, bl1);
                mma8(acc[1][nt], ah[1], bl0, bl1);
            }
        }
    }

    // epilogue: bias + relu + store
    #pragma unroll
    for (int mt = 0; mt < 2; mt++) {
        int gr = row0 + 2*wm + mt;
        if (gr < HF) {
            int pixA = gr*WF + col0 + g;
            int pixB = pixA + 8;
            #pragma unroll
            for (int nt = 0; nt < 4; nt++) {
                int col = n0 + wn*32 + nt*8 + 2*tg;
                float bb0 = b1[col], bb1 = b1[col + 1];
                float2 oA, oB;
                oA.x = fmaxf(acc[mt][nt][0] + bb0, 0.f);
                oA.y = fmaxf(acc[mt][nt][1] + bb1, 0.f);
                oB.x = fmaxf(acc[mt][nt][2] + bb0, 0.f);
                oB.y = fmaxf(acc[mt][nt][3] + bb1, 0.f);
                *reinterpret_cast<float2*>(g_y + (size_t)pixA*512 + col) = oA;
                *reinterpret_cast<float2*>(g_y + (size_t)pixB*512 + col) = oB;
            }
        }
    }
}

// ---------------- 1x1 heads + softmax(9) + deltas ----------------
__global__ __launch_bounds__(384) void heads_kernel(const float* __restrict__ Wc,
                                                    const float* __restrict__ bc,
                                                    const float* __restrict__ Wr,
                                                    const float* __restrict__ br,
                                                    float* __restrict__ out) {
    __shared__ float ys[8*128];
    __shared__ float ws[128*45];
    __shared__ float lg[8][9];

    int t  = threadIdx.x;
    int p0 = blockIdx.x * 8;
    int pp = t / 45, o = t - pp*45;

    float acc = 0.f;
    for (int c0 = 0; c0 < 512; c0 += 128) {
        __syncthreads();
        for (int idx = t; idx < 256; idx += 384) {
            int pix = idx >> 5, v = idx & 31;
            *reinterpret_cast<float4*>(ys + pix*128 + v*4) =
                *reinterpret_cast<const float4*>(g_y + (size_t)(p0+pix)*512 + c0 + v*4);
        }
        for (int idx = t; idx < 5760; idx += 384) {
            int k = idx / 45, oo = idx - k*45;
            ws[idx] = (oo < 9) ? Wc[(c0+k)*9 + oo] : Wr[(c0+k)*36 + (oo-9)];
        }
        __syncthreads();
        if (t < 360) {
            const float4* yv = reinterpret_cast<const float4*>(ys + pp*128);
            #pragma unroll 8
            for (int k4 = 0; k4 < 32; k4++) {
                float4 y4 = yv[k4];
                acc = fmaf(y4.x, ws[(k4*4+0)*45+o], acc);
                acc = fmaf(y4.y, ws[(k4*4+1)*45+o], acc);
                acc = fmaf(y4.z, ws[(k4*4+2)*45+o], acc);
                acc = fmaf(y4.w, ws[(k4*4+3)*45+o], acc);
            }
        }
    }

    if (t < 360) {
        int gp = p0 + pp;
        if (o < 9) lg[pp][o] = acc + bc[o];
        else       out[NANCH + (size_t)gp*36 + (o-9)] = acc + br[o-9];
    }
    __syncthreads();
    if (t < 360 && o < 9) {
        int gp = p0 + pp;
        float m = lg[pp][0];
        #pragma unroll
        for (int j = 1; j < 9; j++) m = fmaxf(m, lg[pp][j]);
        float sum = 0.f;
        #pragma unroll
        for (int j = 0; j < 9; j++) sum += expf(lg[pp][j]-m);
        out[(size_t)gp*9 + o] = expf(lg[pp][o]-m)/sum;
    }
}

// ---------------- exact top-k(6000) via 2-level radix ----------------
__global__ void zero_kernel() {
    int i = blockIdx.x*blockDim.x + threadIdx.x;
    if (i < 65536) g_hist1[i] = 0u;
    else if (i < 131072) g_hist2[i-65536] = 0u;
    else if (i == 131072) { g_cnt_gt = 0u; g_eq_cnt = 0u; }
}

__global__ void hist1_kernel(const float* __restrict__ out) {
    int i = blockIdx.x*blockDim.x + threadIdx.x;
    if (i < NANCH) {
        unsigned u = __float_as_uint(out[i]);
        atomicAdd(&g_hist1[u >> 16], 1u);
    }
}

__global__ void find_bin1_kernel() {
    __shared__ unsigned csum[1024];
    int t = threadIdx.x;
    unsigned s = 0;
    for (int b = 0; b < 64; b++) s += g_hist1[t*64+b];
    csum[t] = s;
    __syncthreads();
    if (t == 0) {
        unsigned cum = 0; int chunk = 0;
        for (int q = 1023; q >= 0; q--) {
            if (cum + csum[q] >= (unsigned)PRE_NMS) { chunk = q; break; }
            cum += csum[q];
        }
        unsigned B = 0;
        for (int b = chunk*64+63; b >= chunk*64; b--) {
            unsigned h = g_hist1[b];
            if (cum + h >= (unsigned)PRE_NMS) { B = (unsigned)b; break; }
            cum += h;
        }
        g_binB = B; g_rank_before = cum;
    }
}

__global__ void hist2_kernel(const float* __restrict__ out) {
    int i = blockIdx.x*blockDim.x + threadIdx.x;
    if (i < NANCH) {
        unsigned u = __float_as_uint(out[i]);
        if ((u >> 16) == g_binB) atomicAdd(&g_hist2[u & 0xFFFFu], 1u);
    }
}

__global__ void find_thresh_kernel() {
    __shared__ unsigned csum[1024];
    int t = threadIdx.x;
    unsigned s = 0;
    for (int b = 0; b < 64; b++) s += g_hist2[t*64+b];
    csum[t] = s;
    __syncthreads();
    if (t == 0) {
        unsigned cum = g_rank_before; int chunk = 0;
        for (int q = 1023; q >= 0; q--) {
            if (cum + csum[q] >= (unsigned)PRE_NMS) { chunk = q; break; }
            cum += csum[q];
        }
        unsigned L = 0;
        for (int b = chunk*64+63; b >= chunk*64; b--) {
            unsigned h = g_hist2[b];
            if (cum + h >= (unsigned)PRE_NMS) { L = (unsigned)b; break; }
            cum += h;
        }
        g_T = (g_binB << 16) | L;
        g_G = cum;
        g_need_eq = (unsigned)PRE_NMS - cum;
    }
}

__global__ void compact_kernel(const float* __restrict__ out) {
    int i = blockIdx.x*blockDim.x + threadIdx.x;
    if (i < NANCH) {
        unsigned u = __float_as_uint(out[i]);
        unsigned T = g_T;
        if (u > T) {
            unsigned pos = atomicAdd(&g_cnt_gt, 1u);
            g_pairs[pos] = (((unsigned long long)u) << 32) | (unsigned)(~(unsigned)i);
        } else if (u == T) {
            unsigned pos = atomicAdd(&g_eq_cnt, 1u);
            g_eq_idx[pos] = (unsigned)i;
        }
    }
}

__global__ void eq_rank_kernel() {
    unsigned E = g_eq_cnt, need = g_need_eq, G = g_G, T = g_T;
    for (unsigned e = blockIdx.x*blockDim.x + threadIdx.x; e < E; e += gridDim.x*blockDim.x) {
        unsigned idx = g_eq_idx[e];
        unsigned rank = 0;
        for (unsigned f = 0; f < E; f++) rank += (g_eq_idx[f] < idx) ? 1u : 0u;
        if (rank < need)
            g_pairs[G + rank] = (((unsigned long long)T) << 32) | (unsigned)(~idx);
    }
}

__global__ void sort_kernel() {
    extern __shared__ unsigned long long sk[];
    int t = threadIdx.x;
    for (int j = t; j < 8192; j += 1024) sk[j] = (j < PRE_NMS) ? g_pairs[j] : 0ULL;
    __syncthreads();
    for (int k = 2; k <= 8192; k <<= 1) {
        for (int j = k >> 1; j > 0; j >>= 1) {
            for (int idx = t; idx < 8192; idx += 1024) {
                int ixj = idx ^ j;
                if (ixj > idx) {
                    unsigned long long a = sk[idx], b = sk[ixj];
                    bool desc = (idx & k) == 0;
                    if (desc ? (a < b) : (a > b)) { sk[idx] = b; sk[ixj] = a; }
                }
            }
            __syncthreads();
        }
    }
    for (int j = t; j < PRE_NMS; j += 1024) {
        unsigned long long p = sk[j];
        unsigned u = (unsigned)(p >> 32);
        unsigned idx = ~((unsigned)p);
        g_top_idx[j] = (int)idx;
        g_top_score[j] = __uint_as_float(u);
    }
}

__global__ void decode_kernel(const float* __restrict__ amap, const float* __restrict__ out) {
    int j = blockIdx.x*blockDim.x + threadIdx.x;
    if (j < PRE_NMS) {
        int idx = g_top_idx[j];
        float4 a = *reinterpret_cast<const float4*>(amap + (size_t)idx*4);
        float4 d = *reinterpret_cast<const float4*>(out + NANCH + (size_t)idx*4);
        float cy = a.x + d.x * a.z;
        float cx = a.y + d.y * a.w;
        float hh = a.z * expf(d.z);
        float ww = a.w * expf(d.w);
        float y1 = cy - 0.5f*hh, x1 = cx - 0.5f*ww;
        float y2 = cy + 0.5f*hh, x2 = cx + 0.5f*ww;
        y1 = fmaxf(y1, 0.f); x1 = fmaxf(x1, 0.f);
        y2 = fminf(y2, IMG_H); x2 = fminf(x2, IMG_W);
        float bh = y2 - y1, bw = x2 - x1;
        bool valid = (bh >= 16.f) && (bw >= 16.f);
        g_by1[j] = y1; g_bx1[j] = x1; g_by2[j] = y2; g_bx2[j] = x2;
        g_nsc[j] = valid ? g_top_score[j] : NEGV;
    }
}

// ---------------- NMS: sorted-order pointer walk + parallel suppression ----------------
// Boxes are in lax.top_k order (score desc, idx asc) == the order argmax scans.
// argmax(remaining) == first unsuppressed entry; invalid boxes pre-marked suppressed.
// When none remain: ok=false forever -> zero rows (identical to reference semantics).
__global__ void nms_kernel(float* __restrict__ out) {
    extern __shared__ float sm[];
    float *sy1 = sm, *sx1 = sm+6000, *sy2 = sm+12000, *sx2 = sm+18000, *sar = sm+24000;
    unsigned char* sup = (unsigned char*)(sm + 30000);
    __shared__ int s_ptr;
    int t = threadIdx.x;

    for (int j = t; j < PRE_NMS; j += 1024) {
        float y1 = g_by1[j], x1 = g_bx1[j], y2 = g_by2[j], x2 = g_bx2[j];
        sy1[j] = y1; sx1[j] = x1; sy2[j] = y2; sx2[j] = x2;
        sar[j] = (y2 - y1) * (x2 - x1);
        sup[j] = (g_nsc[j] == NEGV) ? 1 : 0;
    }
    if (t == 0) s_ptr = 0;
    __syncthreads();

    for (int r = 0; r < POST_NMS; r++) {
        // warp 0: advance pointer to first unsuppressed
        if (t < 32) {
            int p = s_ptr;
            while (p < PRE_NMS) {
                int idx = p + t;
                int a = (idx < PRE_NMS) ? (int)sup[idx] : 0;   // OOB counts as "alive" (stop)
                unsigned m = __ballot_sync(0xffffffffu, a == 0);
                if (m) { p += __ffs(m) - 1; break; }
                p += 32;
            }
            if (p > PRE_NMS) p = PRE_NMS;
            if (t == 0) s_ptr = p;
        }
        __syncthreads();

        int best = s_ptr;
        bool ok = best < PRE_NMS;
        if (ok) {
            float by1 = sy1[best], bx1 = sx1[best], by2 = sy2[best], bx2 = sx2[best], ba = sar[best];
            for (int j = best + 1 + t; j < PRE_NMS; j += 1024) {
                if (!sup[j]) {
                    float iy1 = fmaxf(sy1[j], by1), ix1 = fmaxf(sx1[j], bx1);
                    float iy2 = fminf(sy2[j], by2), ix2 = fminf(sx2[j], bx2);
                    float inter = fmaxf(iy2 - iy1, 0.f) * fmaxf(ix2 - ix1, 0.f);
                    float iou = inter / (sar[j] + ba - inter + 1e-8f);
                    if (iou > 0.7f) sup[j] = 1;
                }
            }
            if (t == 0) {
                sup[best] = 1;
                reinterpret_cast<float4*>(out + NANCH + NANCH*4)[r] =
                    make_float4(by1, bx1, by2, bx2);
            }
        } else if (t == 0) {
            reinterpret_cast<float4*>(out + NANCH + NANCH*4)[r] =
                make_float4(0.f, 0.f, 0.f, 0.f);
        }
        __syncthreads();
    }
}

// ---------------- launch ----------------
extern "C" void kernel_launch(void* const* d_in, const int* in_sizes, int n_in,
                              void* d_out, int out_size) {
    const float* fm   = (const float*)d_in[1];
    const float* amap = (const float*)d_in[2];
    const float* W1   = (const float*)d_in[3];
    const float* b1   = (const float*)d_in[4];
    const float* Wc   = (const float*)d_in[5];
    const float* bc   = (const float*)d_in[6];
    const float* Wr   = (const float*)d_in[7];
    const float* br   = (const float*)d_in[8];
    float* out = (float*)d_out;

    cudaFuncSetAttribute(sort_kernel, cudaFuncAttributeMaxDynamicSharedMemorySize, 8192*8);
    cudaFuncSetAttribute(nms_kernel,  cudaFuncAttributeMaxDynamicSharedMemorySize, 30000*4 + 6000);
    cudaFuncSetAttribute(conv_mma_kernel, cudaFuncAttributeMaxDynamicSharedMemorySize, CONV_SMEM);

    pack_fm_kernel<<<32000, 256>>>(fm);
    pack_w_kernel<<<9216, 256>>>(W1);
    zero_kernel<<<513, 256>>>();

    conv_mma_kernel<<<dim3(10, 13, 8), 256, CONV_SMEM>>>(b1);

    heads_kernel<<<2000, 384>>>(Wc, bc, Wr, br, out);
    hist1_kernel<<<563, 256>>>(out);
    find_bin1_kernel<<<1, 1024>>>();
    hist2_kernel<<<563, 256>>>(out);
    find_thresh_kernel<<<1, 1024>>>();
    compact_kernel<<<563, 256>>>(out);
    eq_rank_kernel<<<32, 256>>>();
    sort_kernel<<<1, 1024, 8192*8>>>();
    decode_kernel<<<24, 256>>>(amap, out);
    nms_kernel<<<1, 1024, 30000*4 + 6000>>>(out);
}

// round 6
// speedup vs baseline: 1.8077x; 1.3232x over previous
#include <cuda_runtime.h>
#include <cuda_fp16.h>
#include <math.h>
#include <stdint.h>

#define HF 100
#define WF 160
#define CIN 512
#define CC 512
#define NA 9
#define NPIX (HF*WF)
#define NANCH (NPIX*NA)      // 144000
#define PRE_NMS 6000
#define POST_NMS 300
#define NEGV -1e9f
#define IMG_H 1600.0f
#define IMG_W 2560.0f

// ---------------- device scratch (no allocations allowed) ----------------
__device__ float  g_y[NPIX*CC];                // conv output (relu'd), 32.8 MB
__device__ __half g_fm_h[NPIX*CIN];            // fp16 hi of feature map
__device__ __half g_fm_l[NPIX*CIN];            // fp16 lo*2048
__device__ __half g_w_h[9*CC*CIN];             // [tap][co][cin] hi
__device__ __half g_w_l[9*CC*CIN];             // lo*2048
__device__ unsigned int g_hist1[65536];
__device__ unsigned int g_hist2[65536];
__device__ unsigned int g_binB, g_rank_before, g_T, g_G, g_need_eq;
__device__ unsigned int g_cnt_gt, g_eq_cnt;
__device__ unsigned long long g_pairs[8192];
__device__ unsigned int g_eq_idx[NANCH];
__device__ int   g_top_idx[PRE_NMS];
__device__ float g_top_score[PRE_NMS];
__device__ float g_by1[PRE_NMS], g_bx1[PRE_NMS], g_by2[PRE_NMS], g_bx2[PRE_NMS];
__device__ float g_nsc[PRE_NMS];

// ================= helpers =================
static __device__ __forceinline__ uint32_t smem_u32(const void* p) {
    uint32_t a;
    asm("{ .reg .u64 t; cvta.to.shared.u64 t, %1; cvt.u32.u64 %0, t; }" : "=r"(a) : "l"(p));
    return a;
}
static __device__ __forceinline__ void cpa16(uint32_t dst, const void* src, uint32_t sz) {
    asm volatile("cp.async.cg.shared.global [%0], [%1], 16, %2;" :: "r"(dst), "l"(src), "r"(sz) : "memory");
}
static __device__ __forceinline__ void cpa16f(uint32_t dst, const void* src) {
    asm volatile("cp.async.cg.shared.global [%0], [%1], 16;" :: "r"(dst), "l"(src) : "memory");
}
#define CP_COMMIT() asm volatile("cp.async.commit_group;" ::: "memory")
#define CP_WAIT1()  asm volatile("cp.async.wait_group 1;" ::: "memory")

static __device__ __forceinline__ void ldsm4(uint32_t* r, uint32_t addr) {
    asm volatile("ldmatrix.sync.aligned.m8n8.x4.shared.b16 {%0,%1,%2,%3}, [%4];"
        : "=r"(r[0]), "=r"(r[1]), "=r"(r[2]), "=r"(r[3]) : "r"(addr));
}
// mma m16n8k16 f16 inputs, f32 accum (baseline PTX sm_80+)
static __device__ __forceinline__ void mma16(float* d, const uint32_t* a, uint32_t b0, uint32_t b1) {
    asm volatile(
        "mma.sync.aligned.m16n8k16.row.col.f32.f16.f16.f32 "
        "{%0,%1,%2,%3}, {%4,%5,%6,%7}, {%8,%9}, {%0,%1,%2,%3};"
        : "+f"(d[0]), "+f"(d[1]), "+f"(d[2]), "+f"(d[3])
        : "r"(a[0]), "r"(a[1]), "r"(a[2]), "r"(a[3]), "r"(b0), "r"(b1));
}

// ================= packing (fp16 hi + scaled lo) =================
__global__ void pack_fm_kernel(const float* __restrict__ fm) {
    int i = blockIdx.x*blockDim.x + threadIdx.x;
    if (i < NPIX*CIN) {
        float x = fm[i];
        __half h = __float2half_rn(x);
        float  r = x - __half2float(h);
        g_fm_h[i] = h;
        g_fm_l[i] = __float2half_rn(r * 2048.0f);
    }
}
__global__ void pack_w_kernel(const float* __restrict__ W1) {
    int i = blockIdx.x*blockDim.x + threadIdx.x;
    if (i < 9*CIN*CC) {
        int tap = i / (CIN*CC), rem = i - tap*(CIN*CC);
        int cin = rem >> 9, co = rem & 511;           // W1 is [tap][cin][co]
        float x = W1[i];
        __half h = __float2half_rn(x);
        float  r = x - __half2float(h);
        size_t dst = ((size_t)tap*CC + co)*CIN + cin; // [tap][co][cin]
        g_w_h[dst] = h;
        g_w_l[dst] = __float2half_rn(r * 2048.0f);
    }
}

// ================= conv 3x3 512->512 via mma.sync fp16 (3-term split) =================
// CTA tile: 8x16 pixels (halo 10x18) x 64 co. 256 threads, 8 warps (4 M x 2 N).
// 288 iterations (32 cin-chunks of 16 x 9 taps); A reused across taps.
// Rows padded to 48B (16B-aligned for cp.async; 12-bank stride -> conflict-free ldmatrix).
#define ROWB  48
#define SEG_A (180*ROWB)       // 8640 (one of hi/lo)
#define ABUF  (2*SEG_A)        // 17280
#define SEG_B (64*ROWB)        // 3072
#define BSTG  (2*SEG_B)        // 6144
#define BOFF  (2*ABUF)         // 34560
#define CONV_SMEM (BOFF + 3*BSTG)   // 52992 B

__global__ __launch_bounds__(256, 2) void conv_mma_kernel(const float* __restrict__ b1) {
    extern __shared__ char smraw[];
    uint32_t sb = smem_u32(smraw);
    int t = threadIdx.x;
    int row0 = blockIdx.y * 8;
    int col0 = blockIdx.x * 16;
    int n0   = blockIdx.z * 64;
    int wid = t >> 5, lane = t & 31;
    int g = lane >> 2, tg = lane & 3;
    int wm = wid >> 1, wn = wid & 1;
    int r8 = lane & 7, sel = lane >> 3;

    // ldmatrix lane-offsets (bytes, before tap shift / buffer base)
    // A: reg order a0(px0-7,k0-7) a1(px8-15,k0-7) a2(px0-7,k8-15) a3(px8-15,k8-15)
    uint32_t aOff[2];
    {
        int apix = r8 + ((sel & 1) ? 8 : 0);
        int akb  = (sel & 2) ? 16 : 0;
        #pragma unroll
        for (int mt = 0; mt < 2; mt++)
            aOff[mt] = (uint32_t)(((2*wm + mt)*18 + apix)*ROWB + akb);
    }
    // B: reg order b0(co0-7,k0-7) b1(co0-7,k8-15) b2(co8-15,k0-7) b3(co8-15,k8-15)
    uint32_t bOff[2];
    {
        int bco = r8 + ((sel & 2) ? 8 : 0);
        int bkb = (sel & 1) ? 16 : 0;
        #pragma unroll
        for (int q = 0; q < 2; q++)
            bOff[q] = (uint32_t)((wn*32 + q*16 + bco)*ROWB + bkb);
    }

    float accD[2][4][4], accE[2][4][4];
    #pragma unroll
    for (int mt = 0; mt < 2; mt++)
        #pragma unroll
        for (int nt = 0; nt < 4; nt++)
            #pragma unroll
            for (int v = 0; v < 4; v++) { accD[mt][nt][v] = 0.f; accE[mt][nt][v] = 0.f; }

    auto loadA = [&](int buf, int cc) {
        uint32_t Ab = sb + buf*ABUF;
        #pragma unroll 1
        for (int o = t; o < 720; o += 256) {
            int pix = o >> 2, part = o & 3;
            int seg = part >> 1, hh = part & 1;
            int hr = pix / 18, hc = pix - hr*18;
            int gr = row0 - 1 + hr, gc = col0 - 1 + hc;
            bool v = ((unsigned)gr < (unsigned)HF) && ((unsigned)gc < (unsigned)WF);
            const __half* base = seg ? g_fm_l : g_fm_h;
            const __half* src = v ? (base + (size_t)(gr*WF + gc)*CIN + cc*16 + hh*8) : base;
            cpa16(Ab + (uint32_t)(seg*SEG_A + pix*ROWB + hh*16), src, v ? 16u : 0u);
        }
    };
    auto loadB = [&](int buf, int tap, int cc) {
        uint32_t Bb = sb + BOFF + buf*BSTG;
        int co = t >> 2, part = t & 3;
        int seg = part >> 1, hh = part & 1;
        const __half* base = seg ? g_w_l : g_w_h;
        cpa16f(Bb + (uint32_t)(seg*SEG_B + co*ROWB + hh*16),
               base + ((size_t)tap*CC + n0 + co)*CIN + cc*16 + hh*8);
    };

    // prologue: groups for it=0 and it=1
    loadA(0, 0);
    loadB(0, 0, 0);
    CP_COMMIT();
    loadB(1, 1, 0);
    CP_COMMIT();

    for (int it = 0; it < 288; it++) {
        CP_WAIT1();
        __syncthreads();
        if (it < 286) {
            int nx = it + 2;
            int ncc = nx / 9, ntap = nx - ncc*9;
            if (ntap == 0) loadA(ncc & 1, ncc);
            loadB(nx % 3, ntap, ncc);
        }
        CP_COMMIT();

        int cc = it / 9, tap = it - cc*9;
        uint32_t tapAdd = (uint32_t)(((tap/3)*18 + (tap%3))*ROWB);
        uint32_t Ab = sb + (cc & 1)*ABUF + tapAdd;
        uint32_t Bb = sb + BOFF + (it % 3)*BSTG;

        uint32_t a_h[2][4], a_l[2][4], b_h[2][4], b_l[2][4];
        #pragma unroll
        for (int mt = 0; mt < 2; mt++) {
            ldsm4(a_h[mt], Ab + aOff[mt]);
            ldsm4(a_l[mt], Ab + SEG_A + aOff[mt]);
        }
        #pragma unroll
        for (int q = 0; q < 2; q++) {
            ldsm4(b_h[q], Bb + bOff[q]);
            ldsm4(b_l[q], Bb + SEG_B + bOff[q]);
        }

        #pragma unroll
        for (int mt = 0; mt < 2; mt++)
            #pragma unroll
            for (int nt = 0; nt < 4; nt++) {
                int q = nt >> 1, h2 = (nt & 1)*2;
                mma16(accD[mt][nt], a_h[mt], b_h[q][h2], b_h[q][h2+1]);
                mma16(accE[mt][nt], a_l[mt], b_h[q][h2], b_h[q][h2+1]);
                mma16(accE[mt][nt], a_h[mt], b_l[q][h2], b_l[q][h2+1]);
            }
    }

    // epilogue: combine split terms + bias + relu + store
    const float INV2048 = 1.0f/2048.0f;
    #pragma unroll
    for (int mt = 0; mt < 2; mt++) {
        int gr = row0 + 2*wm + mt;
        if (gr < HF) {
            int pixA = gr*WF + col0 + g;
            int pixB = pixA + 8;
            #pragma unroll
            for (int nt = 0; nt < 4; nt++) {
                int col = n0 + wn*32 + nt*8 + 2*tg;
                float bb0 = b1[col], bb1 = b1[col + 1];
                float2 oA, oB;
                oA.x = fmaxf(accD[mt][nt][0] + accE[mt][nt][0]*INV2048 + bb0, 0.f);
                oA.y = fmaxf(accD[mt][nt][1] + accE[mt][nt][1]*INV2048 + bb1, 0.f);
                oB.x = fmaxf(accD[mt][nt][2] + accE[mt][nt][2]*INV2048 + bb0, 0.f);
                oB.y = fmaxf(accD[mt][nt][3] + accE[mt][nt][3]*INV2048 + bb1, 0.f);
                *reinterpret_cast<float2*>(g_y + (size_t)pixA*512 + col) = oA;
                *reinterpret_cast<float2*>(g_y + (size_t)pixB*512 + col) = oB;
            }
        }
    }
}

// ---------------- 1x1 heads + softmax(9) + deltas ----------------
__global__ __launch_bounds__(384) void heads_kernel(const float* __restrict__ Wc,
                                                    const float* __restrict__ bc,
                                                    const float* __restrict__ Wr,
                                                    const float* __restrict__ br,
                                                    float* __restrict__ out) {
    __shared__ float ys[8*128];
    __shared__ float ws[128*45];
    __shared__ float lg[8][9];

    int t  = threadIdx.x;
    int p0 = blockIdx.x * 8;
    int pp = t / 45, o = t - pp*45;

    float acc = 0.f;
    for (int c0 = 0; c0 < 512; c0 += 128) {
        __syncthreads();
        for (int idx = t; idx < 256; idx += 384) {
            int pix = idx >> 5, v = idx & 31;
            *reinterpret_cast<float4*>(ys + pix*128 + v*4) =
                *reinterpret_cast<const float4*>(g_y + (size_t)(p0+pix)*512 + c0 + v*4);
        }
        for (int idx = t; idx < 5760; idx += 384) {
            int k = idx / 45, oo = idx - k*45;
            ws[idx] = (oo < 9) ? Wc[(c0+k)*9 + oo] : Wr[(c0+k)*36 + (oo-9)];
        }
        __syncthreads();
        if (t < 360) {
            const float4* yv = reinterpret_cast<const float4*>(ys + pp*128);
            #pragma unroll 8
            for (int k4 = 0; k4 < 32; k4++) {
                float4 y4 = yv[k4];
                acc = fmaf(y4.x, ws[(k4*4+0)*45+o], acc);
                acc = fmaf(y4.y, ws[(k4*4+1)*45+o], acc);
                acc = fmaf(y4.z, ws[(k4*4+2)*45+o], acc);
                acc = fmaf(y4.w, ws[(k4*4+3)*45+o], acc);
            }
        }
    }

    if (t < 360) {
        int gp = p0 + pp;
        if (o < 9) lg[pp][o] = acc + bc[o];
        else       out[NANCH + (size_t)gp*36 + (o-9)] = acc + br[o-9];
    }
    __syncthreads();
    if (t < 360 && o < 9) {
        int gp = p0 + pp;
        float m = lg[pp][0];
        #pragma unroll
        for (int j = 1; j < 9; j++) m = fmaxf(m, lg[pp][j]);
        float sum = 0.f;
        #pragma unroll
        for (int j = 0; j < 9; j++) sum += expf(lg[pp][j]-m);
        out[(size_t)gp*9 + o] = expf(lg[pp][o]-m)/sum;
    }
}

// ---------------- exact top-k(6000) via 2-level radix ----------------
__global__ void zero_kernel() {
    int i = blockIdx.x*blockDim.x + threadIdx.x;
    if (i < 65536) g_hist1[i] = 0u;
    else if (i < 131072) g_hist2[i-65536] = 0u;
    else if (i == 131072) { g_cnt_gt = 0u; g_eq_cnt = 0u; }
}

__global__ void hist1_kernel(const float* __restrict__ out) {
    int i = blockIdx.x*blockDim.x + threadIdx.x;
    if (i < NANCH) {
        unsigned u = __float_as_uint(out[i]);
        atomicAdd(&g_hist1[u >> 16], 1u);
    }
}

__global__ void find_bin1_kernel() {
    __shared__ unsigned csum[1024];
    int t = threadIdx.x;
    unsigned s = 0;
    for (int b = 0; b < 64; b++) s += g_hist1[t*64+b];
    csum[t] = s;
    __syncthreads();
    if (t == 0) {
        unsigned cum = 0; int chunk = 0;
        for (int q = 1023; q >= 0; q--) {
            if (cum + csum[q] >= (unsigned)PRE_NMS) { chunk = q; break; }
            cum += csum[q];
        }
        unsigned B = 0;
        for (int b = chunk*64+63; b >= chunk*64; b--) {
            unsigned h = g_hist1[b];
            if (cum + h >= (unsigned)PRE_NMS) { B = (unsigned)b; break; }
            cum += h;
        }
        g_binB = B; g_rank_before = cum;
    }
}

__global__ void hist2_kernel(const float* __restrict__ out) {
    int i = blockIdx.x*blockDim.x + threadIdx.x;
    if (i < NANCH) {
        unsigned u = __float_as_uint(out[i]);
        if ((u >> 16) == g_binB) atomicAdd(&g_hist2[u & 0xFFFFu], 1u);
    }
}

__global__ void find_thresh_kernel() {
    __shared__ unsigned csum[1024];
    int t = threadIdx.x;
    unsigned s = 0;
    for (int b = 0; b < 64; b++) s += g_hist2[t*64+b];
    csum[t] = s;
    __syncthreads();
    if (t == 0) {
        unsigned cum = g_rank_before; int chunk = 0;
        for (int q = 1023; q >= 0; q--) {
            if (cum + csum[q] >= (unsigned)PRE_NMS) { chunk = q; break; }
            cum += csum[q];
        }
        unsigned L = 0;
        for (int b = chunk*64+63; b >= chunk*64; b--) {
            unsigned h = g_hist2[b];
            if (cum + h >= (unsigned)PRE_NMS) { L = (unsigned)b; break; }
            cum += h;
        }
        g_T = (g_binB << 16) | L;
        g_G = cum;
        g_need_eq = (unsigned)PRE_NMS - cum;
    }
}

__global__ void compact_kernel(const float* __restrict__ out) {
    int i = blockIdx.x*blockDim.x + threadIdx.x;
    if (i < NANCH) {
        unsigned u = __float_as_uint(out[i]);
        unsigned T = g_T;
        if (u > T) {
            unsigned pos = atomicAdd(&g_cnt_gt, 1u);
            g_pairs[pos] = (((unsigned long long)u) << 32) | (unsigned)(~(unsigned)i);
        } else if (u == T) {
            unsigned pos = atomicAdd(&g_eq_cnt, 1u);
            g_eq_idx[pos] = (unsigned)i;
        }
    }
}

__global__ void eq_rank_kernel() {
    unsigned E = g_eq_cnt, need = g_need_eq, G = g_G, T = g_T;
    for (unsigned e = blockIdx.x*blockDim.x + threadIdx.x; e < E; e += gridDim.x*blockDim.x) {
        unsigned idx = g_eq_idx[e];
        unsigned rank = 0;
        for (unsigned f = 0; f < E; f++) rank += (g_eq_idx[f] < idx) ? 1u : 0u;
        if (rank < need)
            g_pairs[G + rank] = (((unsigned long long)T) << 32) | (unsigned)(~idx);
    }
}

__global__ void sort_kernel() {
    extern __shared__ unsigned long long sk[];
    int t = threadIdx.x;
    for (int j = t; j < 8192; j += 1024) sk[j] = (j < PRE_NMS) ? g_pairs[j] : 0ULL;
    __syncthreads();
    for (int k = 2; k <= 8192; k <<= 1) {
        for (int j = k >> 1; j > 0; j >>= 1) {
            for (int idx = t; idx < 8192; idx += 1024) {
                int ixj = idx ^ j;
                if (ixj > idx) {
                    unsigned long long a = sk[idx], b = sk[ixj];
                    bool desc = (idx & k) == 0;
                    if (desc ? (a < b) : (a > b)) { sk[idx] = b; sk[ixj] = a; }
                }
            }
            __syncthreads();
        }
    }
    for (int j = t; j < PRE_NMS; j += 1024) {
        unsigned long long p = sk[j];
        unsigned u = (unsigned)(p >> 32);
        unsigned idx = ~((unsigned)p);
        g_top_idx[j] = (int)idx;
        g_top_score[j] = __uint_as_float(u);
    }
}

__global__ void decode_kernel(const float* __restrict__ amap, const float* __restrict__ out) {
    int j = blockIdx.x*blockDim.x + threadIdx.x;
    if (j < PRE_NMS) {
        int idx = g_top_idx[j];
        float4 a = *reinterpret_cast<const float4*>(amap + (size_t)idx*4);
        float4 d = *reinterpret_cast<const float4*>(out + NANCH + (size_t)idx*4);
        float cy = a.x + d.x * a.z;
        float cx = a.y + d.y * a.w;
        float hh = a.z * expf(d.z);
        float ww = a.w * expf(d.w);
        float y1 = cy - 0.5f*hh, x1 = cx - 0.5f*ww;
        float y2 = cy + 0.5f*hh, x2 = cx + 0.5f*ww;
        y1 = fmaxf(y1, 0.f); x1 = fmaxf(x1, 0.f);
        y2 = fminf(y2, IMG_H); x2 = fminf(x2, IMG_W);
        float bh = y2 - y1, bw = x2 - x1;
        bool valid = (bh >= 16.f) && (bw >= 16.f);
        g_by1[j] = y1; g_bx1[j] = x1; g_by2[j] = y2; g_bx2[j] = x2;
        g_nsc[j] = valid ? g_top_score[j] : NEGV;
    }
}

// ---------------- NMS: sorted-order pointer walk + parallel suppression ----------------
__global__ void nms_kernel(float* __restrict__ out) {
    extern __shared__ float sm[];
    float *sy1 = sm, *sx1 = sm+6000, *sy2 = sm+12000, *sx2 = sm+18000, *sar = sm+24000;
    unsigned char* sup = (unsigned char*)(sm + 30000);
    __shared__ int s_ptr;
    int t = threadIdx.x;

    for (int j = t; j < PRE_NMS; j += 1024) {
        float y1 = g_by1[j], x1 = g_bx1[j], y2 = g_by2[j], x2 = g_bx2[j];
        sy1[j] = y1; sx1[j] = x1; sy2[j] = y2; sx2[j] = x2;
        sar[j] = (y2 - y1) * (x2 - x1);
        sup[j] = (g_nsc[j] == NEGV) ? 1 : 0;
    }
    if (t == 0) s_ptr = 0;
    __syncthreads();

    for (int r = 0; r < POST_NMS; r++) {
        if (t < 32) {
            int p = s_ptr;
            while (p < PRE_NMS) {
                int idx = p + t;
                int a = (idx < PRE_NMS) ? (int)sup[idx] : 0;
                unsigned m = __ballot_sync(0xffffffffu, a == 0);
                if (m) { p += __ffs(m) - 1; break; }
                p += 32;
            }
            if (p > PRE_NMS) p = PRE_NMS;
            if (t == 0) s_ptr = p;
        }
        __syncthreads();

        int best = s_ptr;
        bool ok = best < PRE_NMS;
        if (ok) {
            float by1 = sy1[best], bx1 = sx1[best], by2 = sy2[best], bx2 = sx2[best], ba = sar[best];
            for (int j = best + 1 + t; j < PRE_NMS; j += 1024) {
                if (!sup[j]) {
                    float iy1 = fmaxf(sy1[j], by1), ix1 = fmaxf(sx1[j], bx1);
                    float iy2 = fminf(sy2[j], by2), ix2 = fminf(sx2[j], bx2);
                    float inter = fmaxf(iy2 - iy1, 0.f) * fmaxf(ix2 - ix1, 0.f);
                    float iou = inter / (sar[j] + ba - inter + 1e-8f);
                    if (iou > 0.7f) sup[j] = 1;
                }
            }
            if (t == 0) {
                sup[best] = 1;
                reinterpret_cast<float4*>(out + NANCH + NANCH*4)[r] =
                    make_float4(by1, bx1, by2, bx2);
            }
        } else if (t == 0) {
            reinterpret_cast<float4*>(out + NANCH + NANCH*4)[r] =
                make_float4(0.f, 0.f, 0.f, 0.f);
        }
        __syncthreads();
    }
}

// ---------------- launch ----------------
extern "C" void kernel_launch(void* const* d_in, const int* in_sizes, int n_in,
                              void* d_out, int out_size) {
    const float* fm   = (const float*)d_in[1];
    const float* amap = (const float*)d_in[2];
    const float* W1   = (const float*)d_in[3];
    const float* b1   = (const float*)d_in[4];
    const float* Wc   = (const float*)d_in[5];
    const float* bc   = (const float*)d_in[6];
    const float* Wr   = (const float*)d_in[7];
    const float* br   = (const float*)d_in[8];
    float* out = (float*)d_out;

    cudaFuncSetAttribute(sort_kernel, cudaFuncAttributeMaxDynamicSharedMemorySize, 8192*8);
    cudaFuncSetAttribute(nms_kernel,  cudaFuncAttributeMaxDynamicSharedMemorySize, 30000*4 + 6000);
    cudaFuncSetAttribute(conv_mma_kernel, cudaFuncAttributeMaxDynamicSharedMemorySize, CONV_SMEM);

    pack_fm_kernel<<<32000, 256>>>(fm);
    pack_w_kernel<<<9216, 256>>>(W1);
    zero_kernel<<<513, 256>>>();

    conv_mma_kernel<<<dim3(10, 13, 8), 256, CONV_SMEM>>>(b1);

    heads_kernel<<<2000, 384>>>(Wc, bc, Wr, br, out);
    hist1_kernel<<<563, 256>>>(out);
    find_bin1_kernel<<<1, 1024>>>();
    hist2_kernel<<<563, 256>>>(out);
    find_thresh_kernel<<<1, 1024>>>();
    compact_kernel<<<563, 256>>>(out);
    eq_rank_kernel<<<32, 256>>>();
    sort_kernel<<<1, 1024, 8192*8>>>();
    decode_kernel<<<24, 256>>>(amap, out);
    nms_kernel<<<1, 1024, 30000*4 + 6000>>>(out);
}